// round 14
// baseline (speedup 1.0000x reference)
#include <cuda_runtime.h>
#include <math.h>

#define BB   16
#define S1D  96
#define S2D  112
#define HD   384
#define PD   24
#define NCOL 125
#define NR   (BB*(S1D+S2D))
#define EPSF 1e-8f
#define TINYF 1e-13f
#define NEGBIG (-1e30f)

#define K5N  (BB*S1D/2)        // 768
#define K3N  (BB*(S2D/8))      // 224
#define ATT0 (BB*36)           // 576
#define ATT1 (BB*42)           // 672

// ---------------- packed f32x2 helpers ----------------
__device__ __forceinline__ unsigned long long f2_pack(float x, float y) {
    unsigned long long r;
    asm("mov.b64 %0, {%1, %2};" : "=l"(r) : "f"(x), "f"(y));
    return r;
}
__device__ __forceinline__ unsigned long long f2_fma(unsigned long long a, unsigned long long b,
                                                     unsigned long long c) {
    unsigned long long d;
    asm("fma.rn.f32x2 %0, %1, %2, %3;" : "=l"(d) : "l"(a), "l"(b), "l"(c));
    return d;
}
__device__ __forceinline__ void f2_unpack(unsigned long long v, float& x, float& y) {
    asm("mov.b64 {%0, %1}, %2;" : "=f"(x), "=f"(y) : "l"(v));
}

// ---------------- device scratch ----------------
__device__ __align__(256) float g_c1[BB*S1D*HD];
__device__ __align__(256) float g_c2[BB*S2D*HD];
__device__ float g_n1[BB*S1D];
__device__ float g_n2[BB*S2D];
__device__ float g_wn1mp[BB*S1D*PD];
__device__ float g_wn2mp[BB*S2D*PD];
__device__ float g_den1[BB*S1D];
__device__ float g_den2[BB*S2D];
__device__ int   g_ilen1[BB], g_ilen2[BB];
__device__ __align__(256) float g_last1[BB*HD], g_last2[BB*HD];
__device__ __align__(256) float g_cos[BB*S1D*S2D];
__device__ __align__(256) float g_am2[BB*S1D*HD], g_amax2[BB*S1D*HD];
__device__ __align__(256) float g_am1[BB*S2D*HD], g_amax1[BB*S2D*HD];
__device__ __align__(256) float g_mpd[(size_t)BB*PD*S1D*S2D];

// ================= kprep =================
__global__ void kprep(const float* __restrict__ ctx1, const int* __restrict__ m1,
                      const float* __restrict__ ctx2, const int* __restrict__ m2,
                      const float* __restrict__ w_mp) {
    int blk = blockIdx.x, t = threadIdx.x, lane = t & 31, warp = t >> 5;
    if (blk >= NR) {
        int b = blk - NR;
        __shared__ int redi[8];
        __shared__ int s_len1, s_len2;
        int c1 = 0, c2 = 0;
        for (int s = t; s < S1D; s += 128) c1 += (m1[b*S1D + s] != 0);
        for (int s = t; s < S2D; s += 128) c2 += (m2[b*S2D + s] != 0);
        for (int o = 16; o; o >>= 1) {
            c1 += __shfl_xor_sync(0xffffffffu, c1, o);
            c2 += __shfl_xor_sync(0xffffffffu, c2, o);
        }
        if (lane == 0) { redi[warp] = c1; redi[warp + 4] = c2; }
        __syncthreads();
        if (t == 0) {
            int l1 = 0, l2 = 0;
            for (int q = 0; q < 4; q++) { l1 += redi[q]; l2 += redi[q + 4]; }
            s_len1 = l1; s_len2 = l2;
            g_ilen1[b] = l1; g_ilen2[b] = l2;
        }
        __syncthreads();
        int l1 = s_len1, l2 = s_len2;
        int i1 = max(l1 - 1, 0), i2 = max(l2 - 1, 0);
        for (int h = t; h < HD; h += 128) {
            g_last1[b*HD + h] = (l1 > 0) ? ctx1[(size_t)(b*S1D + i1)*HD + h] : 0.f;
            g_last2[b*HD + h] = (l2 > 0) ? ctx2[(size_t)(b*S2D + i2)*HD + h] : 0.f;
        }
        return;
    }
    int r = blk;
    const float* src; const int* msk; float* dstc; float* dstn; float* dstwn;
    if (r < BB*S1D) {
        src = ctx1 + (size_t)r*HD; msk = m1 + r;
        dstc = g_c1 + (size_t)r*HD; dstn = g_n1 + r; dstwn = g_wn1mp + (size_t)r*PD;
    } else {
        int r2 = r - BB*S1D;
        src = ctx2 + (size_t)r2*HD; msk = m2 + r2;
        dstc = g_c2 + (size_t)r2*HD; dstn = g_n2 + r2; dstwn = g_wn2mp + (size_t)r2*PD;
    }
    float m = (*msk != 0) ? 1.f : 0.f;
    __shared__ float csq[HD];
    __shared__ float red[4];
    float part = 0.f;
    for (int h = t; h < HD; h += 128) {
        float v = src[h] * m;
        dstc[h] = v;
        float vq = v*v;
        csq[h] = vq;
        part += vq;
    }
    for (int o = 16; o; o >>= 1) part += __shfl_xor_sync(0xffffffffu, part, o);
    if (lane == 0) red[warp] = part;
    __syncthreads();
    if (t == 0) {
        float s = red[0] + red[1] + red[2] + red[3];
        *dstn = fmaxf(sqrtf(s), EPSF);
    }
    if (t < 96) {
        int p = t >> 2, sub = t & 3;
        const float* wp = w_mp + (size_t)p*HD;
        float a = 0.f;
        for (int h = sub; h < HD; h += 4) {
            float wv = wp[h];
            a = fmaf(wv*wv, csq[h], a);
        }
        a += __shfl_xor_sync(0xffffffffu, a, 1);
        a += __shfl_xor_sync(0xffffffffu, a, 2);
        if (sub == 0) dstwn[p] = sqrtf(a);
    }
}

// ================= kB: k5 (0..767) || k2 (768..2303) =================
struct SmemB5 {
    float Ws[32][25];
    float Bs2[32][114];
    float c1s[2][HD];
};
struct SmemB2 {
    float c1s[HD];
    float cosr[S2D];
    float red[32];
};
#define SMEMB_SZ (sizeof(SmemB5) > sizeof(SmemB2) ? sizeof(SmemB5) : sizeof(SmemB2))

__global__ void __launch_bounds__(128) kB(const float* __restrict__ w_mp,
                                          float* __restrict__ out) {
    __shared__ __align__(16) char smraw[SMEMB_SZ];
    int blk = blockIdx.x;
    int t = threadIdx.x, lane = t & 31, warp = t >> 5;

    if (blk < K5N) {
        // ---------- k5 (R13 version) ----------
        SmemB5* sm = (SmemB5*)smraw;
        int b = blk / (S1D/2);
        int i0 = (blk % (S1D/2)) * 2;
        int iloc = warp >> 1;
        int half = warp & 1;
        int i = i0 + iloc;
        int tp = lane & 3, tj = lane >> 2;
        int len2i = g_ilen2[b];
        int len1i = g_ilen1[b];

        if (i0 >= len1i) {
            if (half == 0) {
                float* orow = out + (size_t)(b*S1D + i)*NCOL;
                if (lane < 24) { orow[27 + lane] = 0.f; orow[51 + lane] = 0.f; }
            }
            return;
        }
        bool active = (i < len1i);

        for (int li = t; li < 2*HD; li += 128)
            sm->c1s[li / HD][li % HD] = g_c1[(size_t)(b*S1D + i0 + li/HD)*HD + (li % HD)];

        unsigned long long acc2[3][7];
        #pragma unroll
        for (int u = 0; u < 3; u++)
            #pragma unroll
            for (int v = 0; v < 7; v++) acc2[u][v] = 0ull;

        for (int h0 = 0; h0 < HD; h0 += 32) {
            __syncthreads();
            for (int li = t; li < 768; li += 128) {
                int p = li >> 5, k = li & 31;
                float wv = w_mp[(size_t)p*HD + h0 + k];
                sm->Ws[k][p] = wv * wv;
            }
            for (int li = t; li < 3584; li += 128) {
                int j = li >> 5, k = li & 31;
                sm->Bs2[k][j] = g_c2[(size_t)(b*S2D + j)*HD + h0 + k];
            }
            __syncthreads();
            if (active) {
                #pragma unroll 4
                for (int k = 0; k < 32; k++) {
                    float cv = sm->c1s[iloc][h0 + k];
                    const unsigned long long* brow =
                        (const unsigned long long*)(&sm->Bs2[k][tj*14]);
                    unsigned long long b2[7];
                    #pragma unroll
                    for (int v = 0; v < 7; v++) b2[v] = brow[v];
                    #pragma unroll
                    for (int u = 0; u < 3; u++) {
                        float a = sm->Ws[k][half*12 + tp*3 + u] * cv;
                        unsigned long long a2 = f2_pack(a, a);
                        #pragma unroll
                        for (int v = 0; v < 7; v++)
                            acc2[u][v] = f2_fma(a2, b2[v], acc2[u][v]);
                    }
                }
            }
        }

        float* orow = out + (size_t)(b*S1D + i)*NCOL;
        if (!active) {
            if (half == 0 && lane < 24) { orow[27 + lane] = 0.f; orow[51 + lane] = 0.f; }
            return;
        }
        float invc = 1.f / fmaxf((float)len2i, TINYF);
        #pragma unroll
        for (int u = 0; u < 3; u++) {
            int p = half*12 + tp*3 + u;
            float wa = g_wn1mp[(size_t)(b*S1D + i)*PD + p];
            float pmax = NEGBIG, psum = 0.f;
            float* drow = g_mpd + ((size_t)(b*PD + p)*S1D + i)*S2D;
            const float* nbrow = g_wn2mp + (size_t)b*S2D*PD + p;
            #pragma unroll
            for (int v2 = 0; v2 < 7; v2++) {
                float d0, d1;
                f2_unpack(acc2[u][v2], d0, d1);
                int j0 = tj*14 + 2*v2, j1 = j0 + 1;
                float e0 = d0 / fmaxf(wa * nbrow[(size_t)j0*PD], TINYF);
                float e1 = d1 / fmaxf(wa * nbrow[(size_t)j1*PD], TINYF);
                drow[j0] = e0;
                drow[j1] = e1;
                if (j0 < len2i) { pmax = fmaxf(pmax, e0); psum += e0; }
                if (j1 < len2i) { pmax = fmaxf(pmax, e1); psum += e1; }
            }
            #pragma unroll
            for (int o = 4; o <= 16; o <<= 1) {
                pmax = fmaxf(pmax, __shfl_xor_sync(0xffffffffu, pmax, o));
                psum += __shfl_xor_sync(0xffffffffu, psum, o);
            }
            if (tj == 0) {
                orow[27 + p] = pmax;
                orow[51 + p] = psum * invc;
            }
        }
        return;
    }

    // ---------- k2 (R13 version) ----------
    SmemB2* sm = (SmemB2*)smraw;
    int r = blk - K5N, b = r / S1D;
    int len2i = g_ilen2[b];
    for (int h = t; h < HD; h += 128) sm->c1s[h] = g_c1[(size_t)r*HD + h];
    float n1 = g_n1[r];
    __syncthreads();
    const float4* c1v = (const float4*)sm->c1s;
    for (int j = warp; j < S2D; j += 4) {
        if (j < len2i) {
            const float4* c2v = (const float4*)(g_c2 + (size_t)(b*S2D + j)*HD);
            float p = 0.f;
            #pragma unroll
            for (int q = 0; q < 3; q++) {
                float4 a = c1v[lane + 32*q];
                float4 bv = c2v[lane + 32*q];
                p += a.x*bv.x + a.y*bv.y + a.z*bv.z + a.w*bv.w;
            }
            for (int o = 16; o; o >>= 1) p += __shfl_xor_sync(0xffffffffu, p, o);
            if (lane == 0) {
                float cv = p / (n1 * g_n2[b*S2D + j]);
                sm->cosr[j] = cv;
                g_cos[(size_t)r*S2D + j] = cv;
            }
        } else if (lane == 0) {
            g_cos[(size_t)r*S2D + j] = 0.f;
        }
    }
    __syncthreads();
    float pm = NEGBIG, ps = 0.f;
    for (int j = t; j < len2i; j += 128) {
        float c = sm->cosr[j];
        ps += c;
        pm = fmaxf(pm, c);
    }
    for (int o = 16; o; o >>= 1) {
        ps += __shfl_xor_sync(0xffffffffu, ps, o);
        pm = fmaxf(pm, __shfl_xor_sync(0xffffffffu, pm, o));
    }
    if (lane == 0) { sm->red[warp] = ps; sm->red[warp + 16] = pm; }
    __syncthreads();
    if (t == 0) {
        float smv = 0.f, mx = NEGBIG;
        for (int q = 0; q < 4; q++) { smv += sm->red[q]; mx = fmaxf(mx, sm->red[q + 16]); }
        g_den1[r] = fmaxf(smv, TINYF);
        float* o1 = out + (size_t)r*NCOL;
        o1[0] = mx;
        o1[1] = smv / fmaxf((float)len2i, TINYF);
    }
}

// ================= katt tile (device fn) =================
struct SmemAtt {
    float cs[32][18];
    float vs[32][68];
};
__device__ __forceinline__ void katt_tile(char* smraw, int b, int m0, int h0, int d) {
    SmemAtt* sm = (SmemAtt*)smraw;
    int t = threadIdx.x;
    int tx = t & 15, ty = t >> 4;
    int klen = (d == 0) ? g_ilen2[b] : g_ilen1[b];

    float acc[2][4], mx[2][4];
    #pragma unroll
    for (int u = 0; u < 2; u++)
        #pragma unroll
        for (int v = 0; v < 4; v++) { acc[u][v] = 0.f; mx[u][v] = NEGBIG; }

    for (int kc = 0; kc < klen; kc += 32) {
        int kv = min(32, klen - kc);
        __syncthreads();
        #pragma unroll
        for (int it = 0; it < 4; it++) {
            int idx = t + it*128;
            if (d == 0) {
                int c = idx & 31, r2 = idx >> 5;
                float val = (kc + c < S2D) ? g_cos[(size_t)(b*S1D + m0 + r2)*S2D + kc + c] : 0.f;
                sm->cs[c][r2] = val;
            } else {
                int mm = idx & 15, k = idx >> 4;
                float val = (kc + k < S1D) ? g_cos[(size_t)(b*S1D + kc + k)*S2D + m0 + mm] : 0.f;
                sm->cs[k][mm] = val;
            }
        }
        const float* vsrc = (d == 0) ? g_c2 : g_c1;
        int vs_rows = (d == 0) ? S2D : S1D;
        #pragma unroll
        for (int it = 0; it < 16; it++) {
            int idx = t + it*128;
            int h = idx & 63, k = idx >> 6;
            float val = (kc + k < vs_rows)
                      ? vsrc[(size_t)(b*vs_rows + kc + k)*HD + h0 + h] : 0.f;
            sm->vs[k][h] = val;
        }
        __syncthreads();
        for (int k = 0; k < kv; k++) {
            float2 a2 = *(const float2*)&sm->cs[k][ty*2];
            float4 b4 = *(const float4*)&sm->vs[k][tx*4];
            float a[2] = {a2.x, a2.y};
            float bv[4] = {b4.x, b4.y, b4.z, b4.w};
            #pragma unroll
            for (int u = 0; u < 2; u++)
                #pragma unroll
                for (int v = 0; v < 4; v++) {
                    float pr = a[u] * bv[v];
                    acc[u][v] = fmaf(a[u], bv[v], acc[u][v]);
                    mx[u][v] = fmaxf(mx[u][v], pr);
                }
        }
    }
    #pragma unroll
    for (int u = 0; u < 2; u++) {
        int m = m0 + ty*2 + u;
        float den = (d == 0) ? g_den1[b*S1D + m] : g_den2[b*S2D + m];
        float invden = 1.f / den;
        float* am = (d == 0) ? (g_am2 + (size_t)(b*S1D + m)*HD)
                             : (g_am1 + (size_t)(b*S2D + m)*HD);
        float* ax = (d == 0) ? (g_amax2 + (size_t)(b*S1D + m)*HD)
                             : (g_amax1 + (size_t)(b*S2D + m)*HD);
        float4 s4 = make_float4(acc[u][0]*invden, acc[u][1]*invden,
                                acc[u][2]*invden, acc[u][3]*invden);
        float4 m4 = make_float4(mx[u][0], mx[u][1], mx[u][2], mx[u][3]);
        *(float4*)&am[h0 + tx*4] = s4;
        *(float4*)&ax[h0 + tx*4] = m4;
    }
}

// ================= kC: k3-128t (0..223) || katt-d0 (224..799) =================
__global__ void __launch_bounds__(128) kC(float* __restrict__ out) {
    __shared__ __align__(16) char smraw[sizeof(SmemAtt)];
    int blk = blockIdx.x;
    int t = threadIdx.x, lane = t & 31, warp = t >> 5;
    if (blk < K3N) {
        float (*sps)[8] = (float(*)[8])smraw;
        float (*spm)[8] = (float(*)[8])(smraw + 4*8*sizeof(float));
        int b = blk / (S2D/8), jg = blk % (S2D/8);
        int j = jg*8 + (t & 7);
        int irow = t >> 3;                 // 0..15
        int len1i = g_ilen1[b];
        float ps = 0.f, pm = NEGBIG;
        #pragma unroll
        for (int p = 0; p < 6; p++) {
            int i = p*16 + irow;
            if (i < len1i) {
                float c = g_cos[(size_t)(b*S1D + i)*S2D + j];
                ps += c;
                pm = fmaxf(pm, c);
            }
        }
        ps += __shfl_xor_sync(0xffffffffu, ps, 8);
        pm = fmaxf(pm, __shfl_xor_sync(0xffffffffu, pm, 8));
        ps += __shfl_xor_sync(0xffffffffu, ps, 16);
        pm = fmaxf(pm, __shfl_xor_sync(0xffffffffu, pm, 16));
        if (lane < 8) { sps[warp][lane] = ps; spm[warp][lane] = pm; }
        __syncthreads();
        if (t < 8) {
            float sm = 0.f, mx = NEGBIG;
            #pragma unroll
            for (int w = 0; w < 4; w++) { sm += sps[w][t]; mx = fmaxf(mx, spm[w][t]); }
            int jj = jg*8 + t;
            g_den2[b*S2D + jj] = fmaxf(sm, TINYF);
            float* o2 = out + (size_t)BB*S1D*NCOL + (size_t)(b*S2D + jj)*NCOL;
            o2[0] = mx;
            o2[1] = sm / fmaxf((float)len1i, TINYF);
        }
        return;
    }
    // katt d0
    int q = blk - K3N;
    int b = q / 36, yy = q % 36;
    int m0 = (yy % 6) * 16, h0 = (yy / 6) * 64;
    if (m0 >= g_ilen1[b]) return;
    katt_tile(smraw, b, m0, h0, 0);
}

// ================= mpmatch row (128 threads) =================
struct SmemMP {
    float v1s[HD];
    float v2s[HD];
    float red[8];
    float s_p1;
};
__device__ __forceinline__ void mpmatch_row(char* smraw,
                                            const float* v1p,
                                            const float* v2p0, const float* v2p1, const float* v2p2,
                                            const float* w_full, const float* w_att,
                                            const float* w_maxatt, float* orow) {
    SmemMP* sm = (SmemMP*)smraw;
    int t = threadIdx.x, lane = t & 31, warp = t >> 5;
    const float* v2ps[3] = {v2p0, v2p1, v2p2};
    const float* wms[3] = {w_full, w_att, w_maxatt};
    const int colSs[3] = {2, 75, 100};

    float p1 = 0.f;
    #pragma unroll
    for (int q = 0; q < 3; q++) {
        int h = t + q*128;
        float a = v1p[h];
        sm->v1s[h] = a;
        p1 = fmaf(a, a, p1);
    }
    for (int o = 16; o; o >>= 1) p1 += __shfl_xor_sync(0xffffffffu, p1, o);
    if (lane == 0) sm->red[warp] = p1;
    __syncthreads();
    if (t == 0) {
        float a = 0.f;
        for (int q = 0; q < 4; q++) a += sm->red[q];
        sm->s_p1 = a;
    }

    int p = t >> 2, sub = t & 3;
    int pc = min(p, PD - 1);

    for (int kind = 0; kind < 3; kind++) {
        __syncthreads();
        const float* v2p = v2ps[kind];
        const float* wm = wms[kind];
        int colS = colSs[kind];
        float pd = 0.f, p2 = 0.f;
        #pragma unroll
        for (int q = 0; q < 3; q++) {
            int h = t + q*128;
            float a = sm->v1s[h], bv = v2p[h];
            sm->v2s[h] = bv;
            pd = fmaf(a, bv, pd);
            p2 = fmaf(bv, bv, p2);
        }
        for (int o = 16; o; o >>= 1) {
            pd += __shfl_xor_sync(0xffffffffu, pd, o);
            p2 += __shfl_xor_sync(0xffffffffu, p2, o);
        }
        if (lane == 0) { sm->red[warp] = pd; sm->red[warp + 4] = p2; }
        __syncthreads();
        if (t == 0) {
            float d = 0.f, bb = 0.f;
            for (int q = 0; q < 4; q++) { d += sm->red[q]; bb += sm->red[q + 4]; }
            orow[colS] = d / (fmaxf(sqrtf(sm->s_p1), EPSF) * fmaxf(sqrtf(bb), EPSF));
        }
        const float* wp = wm + (size_t)pc*HD;
        float ap = 0.f, bp = 0.f, dp = 0.f;
        for (int h = sub; h < HD; h += 4) {
            float wv = wp[h];
            float wsq = wv*wv;
            float x = sm->v1s[h], y = sm->v2s[h];
            ap = fmaf(wsq*x, x, ap);
            bp = fmaf(wsq*y, y, bp);
            dp = fmaf(wsq*x, y, dp);
        }
        ap += __shfl_xor_sync(0xffffffffu, ap, 1);
        bp += __shfl_xor_sync(0xffffffffu, bp, 1);
        dp += __shfl_xor_sync(0xffffffffu, dp, 1);
        ap += __shfl_xor_sync(0xffffffffu, ap, 2);
        bp += __shfl_xor_sync(0xffffffffu, bp, 2);
        dp += __shfl_xor_sync(0xffffffffu, dp, 2);
        if (sub == 0 && p < PD)
            orow[colS + 1 + p] = dp / (fmaxf(sqrtf(ap), EPSF) * fmaxf(sqrtf(bp), EPSF));
    }
}

// ================= kD: katt-d1 (0..671) || mpmatch-dir1 (672..2207) || k6 (2208..2591) =================
#define MPD_SZ (sizeof(SmemAtt) > sizeof(SmemMP) ? sizeof(SmemAtt) : sizeof(SmemMP))
__global__ void __launch_bounds__(128) kD(const float* __restrict__ w_full,
                                          const float* __restrict__ w_att,
                                          const float* __restrict__ w_maxatt,
                                          float* __restrict__ out) {
    __shared__ __align__(16) char smraw[MPD_SZ];
    int blk = blockIdx.x;
    int t = threadIdx.x;
    if (blk < ATT1) {
        int b = blk / 42, yy = blk % 42;
        int m0 = (yy % 7) * 16, h0 = (yy / 7) * 64;
        if (m0 >= g_ilen2[b]) return;
        katt_tile(smraw, b, m0, h0, 1);
        return;
    }
    if (blk < ATT1 + BB*S1D) {
        int r = blk - ATT1;
        int b = r / S1D;
        if ((r % S1D) >= g_ilen1[b]) {
            float* orow = out + (size_t)r*NCOL;
            if (t < 25) { orow[2 + t] = 0.f; orow[75 + t] = 0.f; orow[100 + t] = 0.f; }
            return;
        }
        mpmatch_row(smraw, g_c1 + (size_t)r*HD,
                    g_last2 + (size_t)b*HD, g_am2 + (size_t)r*HD, g_amax2 + (size_t)r*HD,
                    w_full, w_att, w_maxatt, out + (size_t)r*NCOL);
        return;
    }
    // k6
    int rr = blk - ATT1 - BB*S1D;
    int b = rr / PD, p = rr % PD;
    if (t >= S2D) return;
    int len1i = g_ilen1[b];
    const float* base = g_mpd + (size_t)(b*PD + p)*S1D*S2D + t;
    float mA = NEGBIG, mB = NEGBIG, mC = NEGBIG, mD = NEGBIG;
    float sA = 0.f, sB = 0.f, sC = 0.f, sD = 0.f;
    int i = 0;
    for (; i + 4 <= len1i; i += 4) {
        float d0 = base[(size_t)(i+0)*S2D];
        float d1 = base[(size_t)(i+1)*S2D];
        float d2 = base[(size_t)(i+2)*S2D];
        float d3 = base[(size_t)(i+3)*S2D];
        mA = fmaxf(mA, d0); sA += d0;
        mB = fmaxf(mB, d1); sB += d1;
        mC = fmaxf(mC, d2); sC += d2;
        mD = fmaxf(mD, d3); sD += d3;
    }
    for (; i < len1i; i++) {
        float d0 = base[(size_t)i*S2D];
        mA = fmaxf(mA, d0); sA += d0;
    }
    float mxv = fmaxf(fmaxf(mA, mB), fmaxf(mC, mD));
    float smv = (sA + sB) + (sC + sD);
    float* orow = out + (size_t)BB*S1D*NCOL + (size_t)(b*S2D + t)*NCOL;
    orow[27 + p] = mxv;
    orow[51 + p] = smv / fmaxf((float)len1i, TINYF);
}

// ================= kE: mpmatch-dir2 =================
__global__ void __launch_bounds__(128) kE(const float* __restrict__ w_full,
                                          const float* __restrict__ w_att,
                                          const float* __restrict__ w_maxatt,
                                          float* __restrict__ out) {
    __shared__ __align__(16) char smraw[sizeof(SmemMP)];
    int r2 = blockIdx.x;
    int b = r2 / S2D;
    int t = threadIdx.x;
    float* orow = out + (size_t)BB*S1D*NCOL + (size_t)r2*NCOL;
    if ((r2 % S2D) >= g_ilen2[b]) {
        if (t < 25) { orow[2 + t] = 0.f; orow[75 + t] = 0.f; orow[100 + t] = 0.f; }
        return;
    }
    mpmatch_row(smraw, g_c2 + (size_t)r2*HD,
                g_last1 + (size_t)b*HD, g_am1 + (size_t)r2*HD, g_amax1 + (size_t)r2*HD,
                w_full, w_att, w_maxatt, orow);
}

// ---------------- launch ----------------
extern "C" void kernel_launch(void* const* d_in, const int* in_sizes, int n_in,
                              void* d_out, int out_size) {
    const float* ctx1 = (const float*)d_in[0];
    const int* m1 = (const int*)d_in[1];
    const float* ctx2 = (const float*)d_in[2];
    const int* m2 = (const int*)d_in[3];
    const float* w_full = (const float*)d_in[4];
    const float* w_mp = (const float*)d_in[5];
    const float* w_att = (const float*)d_in[6];
    const float* w_maxatt = (const float*)d_in[7];
    float* out = (float*)d_out;

    kprep<<<NR + BB, 128>>>(ctx1, m1, ctx2, m2, w_mp);
    kB<<<K5N + BB*S1D, 128>>>(w_mp, out);                 // k5 || k2
    kC<<<K3N + ATT0, 128>>>(out);                          // k3 || katt-d0
    kD<<<ATT1 + BB*S1D + BB*PD, 128>>>(w_full, w_att, w_maxatt, out);  // katt-d1 || mp1 || k6
    kE<<<BB*S2D, 128>>>(w_full, w_att, w_maxatt, out);     // mp2
}

// round 17
// speedup vs baseline: 1.1762x; 1.1762x over previous
#include <cuda_runtime.h>
#include <math.h>

#define BB   16
#define S1D  96
#define S2D  112
#define HD   384
#define PD   24
#define NCOL 125
#define NR   (BB*(S1D+S2D))
#define EPSF 1e-8f
#define TINYF 1e-13f
#define NEGBIG (-1e30f)

#define K5N  (BB*S1D/2)        // 768

// ---------------- packed f32x2 helpers ----------------
__device__ __forceinline__ unsigned long long f2_pack(float x, float y) {
    unsigned long long r;
    asm("mov.b64 %0, {%1, %2};" : "=l"(r) : "f"(x), "f"(y));
    return r;
}
__device__ __forceinline__ unsigned long long f2_fma(unsigned long long a, unsigned long long b,
                                                     unsigned long long c) {
    unsigned long long d;
    asm("fma.rn.f32x2 %0, %1, %2, %3;" : "=l"(d) : "l"(a), "l"(b), "l"(c));
    return d;
}
__device__ __forceinline__ void f2_unpack(unsigned long long v, float& x, float& y) {
    asm("mov.b64 {%0, %1}, %2;" : "=f"(x), "=f"(y) : "l"(v));
}

// ---------------- device scratch ----------------
__device__ __align__(256) float g_c1[BB*S1D*HD];
__device__ __align__(256) float g_c2[BB*S2D*HD];
__device__ float g_n1[BB*S1D];
__device__ float g_n2[BB*S2D];
__device__ float g_wn1mp[BB*S1D*PD];
__device__ float g_wn2mp[BB*S2D*PD];
__device__ float g_den1[BB*S1D];
__device__ float g_den2[BB*S2D];
__device__ int   g_ilen1[BB], g_ilen2[BB];
__device__ __align__(256) float g_last1[BB*HD], g_last2[BB*HD];
__device__ __align__(256) float g_cos[BB*S1D*S2D];
__device__ __align__(256) float g_am2[BB*S1D*HD], g_amax2[BB*S1D*HD];
__device__ __align__(256) float g_am1[BB*S2D*HD], g_amax1[BB*S2D*HD];
__device__ __align__(256) float g_mpd[(size_t)BB*PD*S1D*S2D];

// ================= kprep =================
__global__ void kprep(const float* __restrict__ ctx1, const int* __restrict__ m1,
                      const float* __restrict__ ctx2, const int* __restrict__ m2,
                      const float* __restrict__ w_mp) {
    int blk = blockIdx.x, t = threadIdx.x, lane = t & 31, warp = t >> 5;
    if (blk >= NR) {
        int b = blk - NR;
        __shared__ int redi[8];
        __shared__ int s_len1, s_len2;
        int c1 = 0, c2 = 0;
        for (int s = t; s < S1D; s += 128) c1 += (m1[b*S1D + s] != 0);
        for (int s = t; s < S2D; s += 128) c2 += (m2[b*S2D + s] != 0);
        for (int o = 16; o; o >>= 1) {
            c1 += __shfl_xor_sync(0xffffffffu, c1, o);
            c2 += __shfl_xor_sync(0xffffffffu, c2, o);
        }
        if (lane == 0) { redi[warp] = c1; redi[warp + 4] = c2; }
        __syncthreads();
        if (t == 0) {
            int l1 = 0, l2 = 0;
            for (int q = 0; q < 4; q++) { l1 += redi[q]; l2 += redi[q + 4]; }
            s_len1 = l1; s_len2 = l2;
            g_ilen1[b] = l1; g_ilen2[b] = l2;
        }
        __syncthreads();
        int l1 = s_len1, l2 = s_len2;
        int i1 = max(l1 - 1, 0), i2 = max(l2 - 1, 0);
        for (int h = t; h < HD; h += 128) {
            g_last1[b*HD + h] = (l1 > 0) ? ctx1[(size_t)(b*S1D + i1)*HD + h] : 0.f;
            g_last2[b*HD + h] = (l2 > 0) ? ctx2[(size_t)(b*S2D + i2)*HD + h] : 0.f;
        }
        return;
    }
    int r = blk;
    const float* src; const int* msk; float* dstc; float* dstn; float* dstwn;
    if (r < BB*S1D) {
        src = ctx1 + (size_t)r*HD; msk = m1 + r;
        dstc = g_c1 + (size_t)r*HD; dstn = g_n1 + r; dstwn = g_wn1mp + (size_t)r*PD;
    } else {
        int r2 = r - BB*S1D;
        src = ctx2 + (size_t)r2*HD; msk = m2 + r2;
        dstc = g_c2 + (size_t)r2*HD; dstn = g_n2 + r2; dstwn = g_wn2mp + (size_t)r2*PD;
    }
    float m = (*msk != 0) ? 1.f : 0.f;
    __shared__ float csq[HD];
    __shared__ float red[4];
    float part = 0.f;
    for (int h = t; h < HD; h += 128) {
        float v = src[h] * m;
        dstc[h] = v;
        float vq = v*v;
        csq[h] = vq;
        part += vq;
    }
    for (int o = 16; o; o >>= 1) part += __shfl_xor_sync(0xffffffffu, part, o);
    if (lane == 0) red[warp] = part;
    __syncthreads();
    if (t == 0) {
        float s = red[0] + red[1] + red[2] + red[3];
        *dstn = fmaxf(sqrtf(s), EPSF);
    }
    if (t < 96) {
        int p = t >> 2, sub = t & 3;
        const float* wp = w_mp + (size_t)p*HD;
        float a = 0.f;
        for (int h = sub; h < HD; h += 4) {
            float wv = wp[h];
            a = fmaf(wv*wv, csq[h], a);
        }
        a += __shfl_xor_sync(0xffffffffu, a, 1);
        a += __shfl_xor_sync(0xffffffffu, a, 2);
        if (sub == 0) dstwn[p] = sqrtf(a);
    }
}

// ================= kB: k5 (0..767) || k2 (768..2303) =================
struct SmemB5 {
    float Ws[32][25];
    float Bs2[32][114];
    float c1s[2][HD];
};
struct SmemB2 {
    float c1s[HD];
    float cosr[S2D];
    float red[32];
};
#define SMEMB_SZ (sizeof(SmemB5) > sizeof(SmemB2) ? sizeof(SmemB5) : sizeof(SmemB2))

__global__ void __launch_bounds__(128) kB(const float* __restrict__ w_mp,
                                          float* __restrict__ out) {
    __shared__ __align__(16) char smraw[SMEMB_SZ];
    int blk = blockIdx.x;
    int t = threadIdx.x, lane = t & 31, warp = t >> 5;

    if (blk < K5N) {
        // ---------- k5 (R13 version, verbatim) ----------
        SmemB5* sm = (SmemB5*)smraw;
        int b = blk / (S1D/2);
        int i0 = (blk % (S1D/2)) * 2;
        int iloc = warp >> 1;
        int half = warp & 1;
        int i = i0 + iloc;
        int tp = lane & 3, tj = lane >> 2;
        int len2i = g_ilen2[b];
        int len1i = g_ilen1[b];

        if (i0 >= len1i) {
            if (half == 0) {
                float* orow = out + (size_t)(b*S1D + i)*NCOL;
                if (lane < 24) { orow[27 + lane] = 0.f; orow[51 + lane] = 0.f; }
            }
            return;
        }
        bool active = (i < len1i);

        for (int li = t; li < 2*HD; li += 128)
            sm->c1s[li / HD][li % HD] = g_c1[(size_t)(b*S1D + i0 + li/HD)*HD + (li % HD)];

        unsigned long long acc2[3][7];
        #pragma unroll
        for (int u = 0; u < 3; u++)
            #pragma unroll
            for (int v = 0; v < 7; v++) acc2[u][v] = 0ull;

        for (int h0 = 0; h0 < HD; h0 += 32) {
            __syncthreads();
            for (int li = t; li < 768; li += 128) {
                int p = li >> 5, k = li & 31;
                float wv = w_mp[(size_t)p*HD + h0 + k];
                sm->Ws[k][p] = wv * wv;
            }
            for (int li = t; li < 3584; li += 128) {
                int j = li >> 5, k = li & 31;
                sm->Bs2[k][j] = g_c2[(size_t)(b*S2D + j)*HD + h0 + k];
            }
            __syncthreads();
            if (active) {
                #pragma unroll 4
                for (int k = 0; k < 32; k++) {
                    float cv = sm->c1s[iloc][h0 + k];
                    const unsigned long long* brow =
                        (const unsigned long long*)(&sm->Bs2[k][tj*14]);
                    unsigned long long b2[7];
                    #pragma unroll
                    for (int v = 0; v < 7; v++) b2[v] = brow[v];
                    #pragma unroll
                    for (int u = 0; u < 3; u++) {
                        float a = sm->Ws[k][half*12 + tp*3 + u] * cv;
                        unsigned long long a2 = f2_pack(a, a);
                        #pragma unroll
                        for (int v = 0; v < 7; v++)
                            acc2[u][v] = f2_fma(a2, b2[v], acc2[u][v]);
                    }
                }
            }
        }

        float* orow = out + (size_t)(b*S1D + i)*NCOL;
        if (!active) {
            if (half == 0 && lane < 24) { orow[27 + lane] = 0.f; orow[51 + lane] = 0.f; }
            return;
        }
        float invc = 1.f / fmaxf((float)len2i, TINYF);
        #pragma unroll
        for (int u = 0; u < 3; u++) {
            int p = half*12 + tp*3 + u;
            float wa = g_wn1mp[(size_t)(b*S1D + i)*PD + p];
            float pmax = NEGBIG, psum = 0.f;
            float* drow = g_mpd + ((size_t)(b*PD + p)*S1D + i)*S2D;
            const float* nbrow = g_wn2mp + (size_t)b*S2D*PD + p;
            #pragma unroll
            for (int v2 = 0; v2 < 7; v2++) {
                float d0, d1;
                f2_unpack(acc2[u][v2], d0, d1);
                int j0 = tj*14 + 2*v2, j1 = j0 + 1;
                float e0 = d0 / fmaxf(wa * nbrow[(size_t)j0*PD], TINYF);
                float e1 = d1 / fmaxf(wa * nbrow[(size_t)j1*PD], TINYF);
                drow[j0] = e0;
                drow[j1] = e1;
                if (j0 < len2i) { pmax = fmaxf(pmax, e0); psum += e0; }
                if (j1 < len2i) { pmax = fmaxf(pmax, e1); psum += e1; }
            }
            #pragma unroll
            for (int o = 4; o <= 16; o <<= 1) {
                pmax = fmaxf(pmax, __shfl_xor_sync(0xffffffffu, pmax, o));
                psum += __shfl_xor_sync(0xffffffffu, psum, o);
            }
            if (tj == 0) {
                orow[27 + p] = pmax;
                orow[51 + p] = psum * invc;
            }
        }
        return;
    }

    // ---------- k2 (R13 version, verbatim) ----------
    SmemB2* sm = (SmemB2*)smraw;
    int r = blk - K5N, b = r / S1D;
    int len2i = g_ilen2[b];
    for (int h = t; h < HD; h += 128) sm->c1s[h] = g_c1[(size_t)r*HD + h];
    float n1 = g_n1[r];
    __syncthreads();
    const float4* c1v = (const float4*)sm->c1s;
    for (int j = warp; j < S2D; j += 4) {
        if (j < len2i) {
            const float4* c2v = (const float4*)(g_c2 + (size_t)(b*S2D + j)*HD);
            float p = 0.f;
            #pragma unroll
            for (int q = 0; q < 3; q++) {
                float4 a = c1v[lane + 32*q];
                float4 bv = c2v[lane + 32*q];
                p += a.x*bv.x + a.y*bv.y + a.z*bv.z + a.w*bv.w;
            }
            for (int o = 16; o; o >>= 1) p += __shfl_xor_sync(0xffffffffu, p, o);
            if (lane == 0) {
                float cv = p / (n1 * g_n2[b*S2D + j]);
                sm->cosr[j] = cv;
                g_cos[(size_t)r*S2D + j] = cv;
            }
        } else if (lane == 0) {
            g_cos[(size_t)r*S2D + j] = 0.f;
        }
    }
    __syncthreads();
    float pm = NEGBIG, ps = 0.f;
    for (int j = t; j < len2i; j += 128) {
        float c = sm->cosr[j];
        ps += c;
        pm = fmaxf(pm, c);
    }
    for (int o = 16; o; o >>= 1) {
        ps += __shfl_xor_sync(0xffffffffu, ps, o);
        pm = fmaxf(pm, __shfl_xor_sync(0xffffffffu, pm, o));
    }
    if (lane == 0) { sm->red[warp] = ps; sm->red[warp + 16] = pm; }
    __syncthreads();
    if (t == 0) {
        float smv = 0.f, mx = NEGBIG;
        for (int q = 0; q < 4; q++) { smv += sm->red[q]; mx = fmaxf(mx, sm->red[q + 16]); }
        g_den1[r] = fmaxf(smv, TINYF);
        float* o1 = out + (size_t)r*NCOL;
        o1[0] = mx;
        o1[1] = smv / fmaxf((float)len2i, TINYF);
    }
}

// ---------------- K3: dir2 col stats + den2 (R13 version) ----------------
__global__ void k3_cos_col(float* __restrict__ out) {
    int blk = blockIdx.x;
    int b = blk / (S2D/8), jg = blk % (S2D/8);
    int t = threadIdx.x, lane = t & 31, warp = t >> 5;
    int j = jg*8 + (t & 7);
    int irow = t >> 3;                 // 0..31
    int len1i = g_ilen1[b];
    __shared__ float sps[8][8], spm[8][8];
    float ps = 0.f, pm = NEGBIG;
    #pragma unroll
    for (int p = 0; p < 3; p++) {
        int i = p*32 + irow;
        if (i < len1i) {
            float c = g_cos[(size_t)(b*S1D + i)*S2D + j];
            ps += c;
            pm = fmaxf(pm, c);
        }
    }
    ps += __shfl_xor_sync(0xffffffffu, ps, 8);
    pm = fmaxf(pm, __shfl_xor_sync(0xffffffffu, pm, 8));
    ps += __shfl_xor_sync(0xffffffffu, ps, 16);
    pm = fmaxf(pm, __shfl_xor_sync(0xffffffffu, pm, 16));
    if (lane < 8) { sps[warp][lane] = ps; spm[warp][lane] = pm; }
    __syncthreads();
    if (t < 8) {
        float sm = 0.f, mx = NEGBIG;
        #pragma unroll
        for (int w = 0; w < 8; w++) { sm += sps[w][t]; mx = fmaxf(mx, spm[w][t]); }
        int jj = jg*8 + t;
        g_den2[b*S2D + jj] = fmaxf(sm, TINYF);
        float* o2 = out + (size_t)BB*S1D*NCOL + (size_t)(b*S2D + jj)*NCOL;
        o2[0] = mx;
        o2[1] = sm / fmaxf((float)len1i, TINYF);
    }
}

// ---------------- katt (R13 version) ----------------
__global__ void __launch_bounds__(128) katt(void) {
    int b = blockIdx.x, y = blockIdx.y, d = blockIdx.z;
    int m0, h0, klen;
    if (d == 0) {
        if (y >= 36) return;
        m0 = (y % 6) * 16; h0 = (y / 6) * 64; klen = g_ilen2[b];
        if (m0 >= g_ilen1[b]) return;
    } else {
        m0 = (y % 7) * 16; h0 = (y / 7) * 64; klen = g_ilen1[b];
        if (m0 >= g_ilen2[b]) return;
    }
    int t = threadIdx.x;
    int tx = t & 15, ty = t >> 4;

    __shared__ __align__(16) float cs[32][18];
    __shared__ __align__(16) float vs[32][68];

    float acc[2][4], mx[2][4];
    #pragma unroll
    for (int u = 0; u < 2; u++)
        #pragma unroll
        for (int v = 0; v < 4; v++) { acc[u][v] = 0.f; mx[u][v] = NEGBIG; }

    for (int kc = 0; kc < klen; kc += 32) {
        int kv = min(32, klen - kc);
        __syncthreads();
        #pragma unroll
        for (int it = 0; it < 4; it++) {
            int idx = t + it*128;
            if (d == 0) {
                int c = idx & 31, r2 = idx >> 5;
                float val = (kc + c < S2D) ? g_cos[(size_t)(b*S1D + m0 + r2)*S2D + kc + c] : 0.f;
                cs[c][r2] = val;
            } else {
                int mm = idx & 15, k = idx >> 4;
                float val = (kc + k < S1D) ? g_cos[(size_t)(b*S1D + kc + k)*S2D + m0 + mm] : 0.f;
                cs[k][mm] = val;
            }
        }
        const float* vsrc = (d == 0) ? g_c2 : g_c1;
        int vs_rows = (d == 0) ? S2D : S1D;
        #pragma unroll
        for (int it = 0; it < 16; it++) {
            int idx = t + it*128;
            int h = idx & 63, k = idx >> 6;
            float val = (kc + k < vs_rows)
                      ? vsrc[(size_t)(b*vs_rows + kc + k)*HD + h0 + h] : 0.f;
            vs[k][h] = val;
        }
        __syncthreads();
        for (int k = 0; k < kv; k++) {
            float2 a2 = *(const float2*)&cs[k][ty*2];
            float4 b4 = *(const float4*)&vs[k][tx*4];
            float a[2] = {a2.x, a2.y};
            float bv[4] = {b4.x, b4.y, b4.z, b4.w};
            #pragma unroll
            for (int u = 0; u < 2; u++)
                #pragma unroll
                for (int v = 0; v < 4; v++) {
                    float pr = a[u] * bv[v];
                    acc[u][v] = fmaf(a[u], bv[v], acc[u][v]);
                    mx[u][v] = fmaxf(mx[u][v], pr);
                }
        }
    }
    #pragma unroll
    for (int u = 0; u < 2; u++) {
        int m = m0 + ty*2 + u;
        float den = (d == 0) ? g_den1[b*S1D + m] : g_den2[b*S2D + m];
        float invden = 1.f / den;
        float* am = (d == 0) ? (g_am2 + (size_t)(b*S1D + m)*HD)
                             : (g_am1 + (size_t)(b*S2D + m)*HD);
        float* ax = (d == 0) ? (g_amax2 + (size_t)(b*S1D + m)*HD)
                             : (g_amax1 + (size_t)(b*S2D + m)*HD);
        float4 s4 = make_float4(acc[u][0]*invden, acc[u][1]*invden,
                                acc[u][2]*invden, acc[u][3]*invden);
        float4 m4 = make_float4(mx[u][0], mx[u][1], mx[u][2], mx[u][3]);
        *(float4*)&am[h0 + tx*4] = s4;
        *(float4*)&ax[h0 + tx*4] = m4;
    }
}

// ---------------- k4ext (R13 192-thread version) + k6 ----------------
__global__ void k4ext(const float* __restrict__ w_full, const float* __restrict__ w_att,
                      const float* __restrict__ w_maxatt, float* __restrict__ out) {
    int r = blockIdx.x;
    int t = threadIdx.x, lane = t & 31, warp = t >> 5;
    if (r >= NR) {
        int rr = r - NR;
        int b = rr / PD, p = rr % PD;
        if (t >= S2D) return;
        int len1i = g_ilen1[b];
        const float* base = g_mpd + (size_t)(b*PD + p)*S1D*S2D + t;
        float mA = NEGBIG, mB = NEGBIG, mC = NEGBIG, mD = NEGBIG;
        float sA = 0.f, sB = 0.f, sC = 0.f, sD = 0.f;
        int i = 0;
        for (; i + 4 <= len1i; i += 4) {
            float d0 = base[(size_t)(i+0)*S2D];
            float d1 = base[(size_t)(i+1)*S2D];
            float d2 = base[(size_t)(i+2)*S2D];
            float d3 = base[(size_t)(i+3)*S2D];
            mA = fmaxf(mA, d0); sA += d0;
            mB = fmaxf(mB, d1); sB += d1;
            mC = fmaxf(mC, d2); sC += d2;
            mD = fmaxf(mD, d3); sD += d3;
        }
        for (; i < len1i; i++) {
            float d0 = base[(size_t)i*S2D];
            mA = fmaxf(mA, d0); sA += d0;
        }
        float mxv = fmaxf(fmaxf(mA, mB), fmaxf(mC, mD));
        float smv = (sA + sB) + (sC + sD);
        float* orow = out + (size_t)BB*S1D*NCOL + (size_t)(b*S2D + t)*NCOL;
        orow[27 + p] = mxv;
        orow[51 + p] = smv / fmaxf((float)len1i, TINYF);
        return;
    }
    const float* v1p;
    float* orow;
    const float *v2ps[3];
    int b;
    bool masked;
    if (r < BB*S1D) {
        b = r / S1D;
        masked = ((r % S1D) >= g_ilen1[b]);
        v1p = g_c1 + (size_t)r*HD;
        orow = out + (size_t)r*NCOL;
        v2ps[0] = g_last2 + (size_t)b*HD;
        v2ps[1] = g_am2 + (size_t)r*HD;
        v2ps[2] = g_amax2 + (size_t)r*HD;
    } else {
        int r2 = r - BB*S1D;
        b = r2 / S2D;
        masked = ((r2 % S2D) >= g_ilen2[b]);
        v1p = g_c2 + (size_t)r2*HD;
        orow = out + (size_t)BB*S1D*NCOL + (size_t)r2*NCOL;
        v2ps[0] = g_last1 + (size_t)b*HD;
        v2ps[1] = g_am1 + (size_t)r2*HD;
        v2ps[2] = g_amax1 + (size_t)r2*HD;
    }
    if (masked) {
        if (t < 25) { orow[2 + t] = 0.f; orow[75 + t] = 0.f; orow[100 + t] = 0.f; }
        return;
    }
    const float* wms[3] = {w_full, w_att, w_maxatt};
    const int colSs[3] = {2, 75, 100};

    __shared__ float v1s[HD], v2s[HD];
    __shared__ float red[18];
    __shared__ float s_p1;
    float p1 = 0.f;
    for (int h = t; h < HD; h += 192) {
        float a = v1p[h];
        v1s[h] = a;
        p1 = fmaf(a, a, p1);
    }
    for (int o = 16; o; o >>= 1) p1 += __shfl_xor_sync(0xffffffffu, p1, o);
    if (lane == 0) red[warp] = p1;
    __syncthreads();
    if (t == 0) {
        float a = 0.f;
        for (int q = 0; q < 6; q++) a += red[q];
        s_p1 = a;
    }

    for (int kind = 0; kind < 3; kind++) {
        __syncthreads();
        const float* v2p = v2ps[kind];
        const float* wm = wms[kind];
        int colS = colSs[kind];
        float pd = 0.f, p2 = 0.f;
        for (int h = t; h < HD; h += 192) {
            float a = v1s[h], bv = v2p[h];
            v2s[h] = bv;
            pd = fmaf(a, bv, pd);
            p2 = fmaf(bv, bv, p2);
        }
        for (int o = 16; o; o >>= 1) {
            pd += __shfl_xor_sync(0xffffffffu, pd, o);
            p2 += __shfl_xor_sync(0xffffffffu, p2, o);
        }
        if (lane == 0) { red[warp] = pd; red[warp + 6] = p2; }
        __syncthreads();
        if (t == 0) {
            float d = 0.f, bb = 0.f;
            for (int q = 0; q < 6; q++) { d += red[q]; bb += red[q + 6]; }
            orow[colS] = d / (fmaxf(sqrtf(s_p1), EPSF) * fmaxf(sqrtf(bb), EPSF));
        }
        int p = t >> 3, sub = t & 7;
        const float* wp = wm + (size_t)p*HD;
        float ap = 0.f, bp = 0.f, dp = 0.f;
        for (int h = sub; h < HD; h += 8) {
            float wv = wp[h];
            float wsq = wv*wv;
            float x = v1s[h], y = v2s[h];
            ap = fmaf(wsq*x, x, ap);
            bp = fmaf(wsq*y, y, bp);
            dp = fmaf(wsq*x, y, dp);
        }
        #pragma unroll
        for (int o = 4; o; o >>= 1) {
            ap += __shfl_xor_sync(0xffffffffu, ap, o);
            bp += __shfl_xor_sync(0xffffffffu, bp, o);
            dp += __shfl_xor_sync(0xffffffffu, dp, o);
        }
        if (sub == 0)
            orow[colS + 1 + p] = dp / (fmaxf(sqrtf(ap), EPSF) * fmaxf(sqrtf(bp), EPSF));
    }
}

// ---------------- launch ----------------
extern "C" void kernel_launch(void* const* d_in, const int* in_sizes, int n_in,
                              void* d_out, int out_size) {
    const float* ctx1 = (const float*)d_in[0];
    const int* m1 = (const int*)d_in[1];
    const float* ctx2 = (const float*)d_in[2];
    const int* m2 = (const int*)d_in[3];
    const float* w_full = (const float*)d_in[4];
    const float* w_mp = (const float*)d_in[5];
    const float* w_att = (const float*)d_in[6];
    const float* w_maxatt = (const float*)d_in[7];
    float* out = (float*)d_out;

    kprep<<<NR + BB, 128>>>(ctx1, m1, ctx2, m2, w_mp);
    kB<<<K5N + BB*S1D, 128>>>(w_mp, out);            // k5 || k2 (the one proven fusion)
    k3_cos_col<<<BB*(S2D/8), 256>>>(out);
    katt<<<dim3(BB, 42, 2), 128>>>();
    k4ext<<<NR + BB*PD, 192>>>(w_full, w_att, w_maxatt, out);
}